// round 13
// baseline (speedup 1.0000x reference)
#include <cuda_runtime.h>
#include <math.h>

#define BATCH 4
#define TQL   128
#define TKL   512
#define ND    512
#define OD    512
#define MROWS (BATCH * TQL)     // 512
#define SLAB  (MROWS * 512)     // one partial slab

// Scratch (device globals -- no allocation allowed)
__device__ __align__(16) float g_ctx  [MROWS * ND];
__device__ __align__(16) float g_part [8 * SLAB];   // attq partials, then ctx partials
__device__ __align__(16) float g_part2[8 * SLAB];   // out-GEMM partials (qhalf 0-3, chalf 4-7)

__device__ __forceinline__ float fast_tanh(float x) {
    float y;
    asm("tanh.approx.f32 %0, %1;" : "=f"(y) : "f"(x));
    return y;
}

// ----------------------------------------------------------------------------
// Split-K NT GEMM body over a K=512 range (register-pipelined inner loop):
//   part[z0+bz][m][n] = sum_{k in chunk bz} A0[m,k] * B[n, boff+k]
// ----------------------------------------------------------------------------
template <int SPLITS>
__device__ __forceinline__ void gemm_body(
    const float* __restrict__ A0, const float* __restrict__ B,
    int bstride, int boff, float* __restrict__ part, int z0,
    int bx, int by, int bz)
{
    constexpr int CHUNK  = 512 / SPLITS;
    constexpr int STAGES = CHUNK / 16;

    __shared__ float As[2][16][68];
    __shared__ float Bs[2][16][68];

    const int tid = threadIdx.x;
    const int r   = tid >> 2;
    const int c   = tid & 3;
    const int ty  = tid >> 4;
    const int tx  = tid & 15;
    const int m0  = by * 64;
    const int n0  = bx * 64;
    const int kst = bz * CHUNK;

    float acc[4][4] = {};

    {
        float4 av = *(const float4*)(A0 + (size_t)(m0 + r) * 512 + kst + 4 * c);
        float4 bv = *(const float4*)(B + (size_t)(n0 + r) * bstride + boff + kst + 4 * c);
        float a4[4] = {av.x, av.y, av.z, av.w};
        float b4[4] = {bv.x, bv.y, bv.z, bv.w};
#pragma unroll
        for (int j = 0; j < 4; j++) {
            As[0][4 * c + j][r] = a4[j];
            Bs[0][4 * c + j][r] = b4[j];
        }
    }
    __syncthreads();

    int buf = 0;
#pragma unroll 1
    for (int s = 0; s < STAGES; s++) {
        float4 anx, bnx;
        if (s + 1 < STAGES) {
            const int kb = kst + (s + 1) * 16;
            anx = *(const float4*)(A0 + (size_t)(m0 + r) * 512 + kb + 4 * c);
            bnx = *(const float4*)(B + (size_t)(n0 + r) * bstride + boff + kb + 4 * c);
        }

        // register-pipelined smem reads
        float4 a_c = *(const float4*)&As[buf][0][ty * 4];
        float4 b_c = *(const float4*)&Bs[buf][0][tx * 4];
#pragma unroll
        for (int kk = 0; kk < 16; kk++) {
            float4 a_n, b_n;
            if (kk < 15) {
                a_n = *(const float4*)&As[buf][kk + 1][ty * 4];
                b_n = *(const float4*)&Bs[buf][kk + 1][tx * 4];
            }
            float a4[4] = {a_c.x, a_c.y, a_c.z, a_c.w};
            float b4[4] = {b_c.x, b_c.y, b_c.z, b_c.w};
#pragma unroll
            for (int i = 0; i < 4; i++)
#pragma unroll
                for (int j = 0; j < 4; j++)
                    acc[i][j] += a4[i] * b4[j];
            if (kk < 15) { a_c = a_n; b_c = b_n; }
        }

        if (s + 1 < STAGES) {
            const int nb = buf ^ 1;
            float a4[4] = {anx.x, anx.y, anx.z, anx.w};
            float b4[4] = {bnx.x, bnx.y, bnx.z, bnx.w};
#pragma unroll
            for (int j = 0; j < 4; j++) {
                As[nb][4 * c + j][r] = a4[j];
                Bs[nb][4 * c + j][r] = b4[j];
            }
            __syncthreads();
            buf = nb;
        }
    }

    float* pp = part + (size_t)(z0 + bz) * SLAB;
#pragma unroll
    for (int i = 0; i < 4; i++) {
        float4 v = make_float4(acc[i][0], acc[i][1], acc[i][2], acc[i][3]);
        *(float4*)&pp[(size_t)(m0 + ty * 4 + i) * 512 + n0 + tx * 4] = v;
    }
}

// ----------------------------------------------------------------------------
// Scores + softmax body: block owns 4 full query rows (all 512 keys).
// 1) cooperative reduce of attq partials + b_q into smem
// 2) scores for 4 q x 512 k (MUFU tanh bound), into smem
// 3) per-row softmax (warps 0-3)
// 4) vectorized probs write
// ----------------------------------------------------------------------------
__device__ __forceinline__ void scores_softmax_body(
    const float* __restrict__ keys,
    const float* __restrict__ w_att,
    const float* __restrict__ b_att,
    const float* __restrict__ b_q,
    float* __restrict__ probs,
    int bi)
{
    __shared__ float s_aq[4][512];   // 8 KB
    __shared__ float s_sc[4][512];   // 8 KB

    const int tid  = threadIdx.x;
    const int wid  = tid >> 5;
    const int lane = tid & 31;
    const int q0   = (bi & 31) << 2;
    const int b    = bi >> 5;

    // 1) fused split-K reduce of att_query (vectorized)
#pragma unroll
    for (int e = 0; e < 2; e++) {
        const int f  = tid + 256 * e;      // float4 index 0..511
        const int q  = f >> 7, ng = f & 127;
        const size_t row4 = ((size_t)(b * TQL + q0 + q) * 512 + ng * 4) / 4;
        float4 s = ((const float4*)b_q)[ng];
#pragma unroll
        for (int sp = 0; sp < 8; sp++) {
            float4 t = ((const float4*)g_part)[(size_t)sp * (SLAB / 4) + row4];
            s.x += t.x; s.y += t.y; s.z += t.z; s.w += t.w;
        }
        *(float4*)&s_aq[q][ng * 4] = s;
    }
    __syncthreads();

    // 2) register-resident w_att + att_query (lane owns 16 n-positions)
    float wreg[16];
    float areg[4][16];
#pragma unroll
    for (int i = 0; i < 4; i++) {
        float4 w4 = *(const float4*)(w_att + i * 128 + lane * 4);
        wreg[i * 4 + 0] = w4.x; wreg[i * 4 + 1] = w4.y;
        wreg[i * 4 + 2] = w4.z; wreg[i * 4 + 3] = w4.w;
#pragma unroll
        for (int q = 0; q < 4; q++) {
            float4 a4 = *(const float4*)&s_aq[q][i * 128 + lane * 4];
            areg[q][i * 4 + 0] = a4.x; areg[q][i * 4 + 1] = a4.y;
            areg[q][i * 4 + 2] = a4.z; areg[q][i * 4 + 3] = a4.w;
        }
    }
    const float batt = b_att[0];
    const float* keyb = keys + (size_t)b * TKL * ND;

    for (int k = wid; k < TKL; k += 8) {
        const float* kr = keyb + (size_t)k * ND;
        float acc0 = 0.f, acc1 = 0.f, acc2 = 0.f, acc3 = 0.f;
#pragma unroll
        for (int i = 0; i < 4; i++) {
            float4 k4 = *(const float4*)(kr + i * 128 + lane * 4);
            float kv[4] = {k4.x, k4.y, k4.z, k4.w};
#pragma unroll
            for (int j = 0; j < 4; j++) {
                const float w = wreg[i * 4 + j];
                acc0 += w * fast_tanh(areg[0][i * 4 + j] + kv[j]);
                acc1 += w * fast_tanh(areg[1][i * 4 + j] + kv[j]);
                acc2 += w * fast_tanh(areg[2][i * 4 + j] + kv[j]);
                acc3 += w * fast_tanh(areg[3][i * 4 + j] + kv[j]);
            }
        }
#pragma unroll
        for (int off = 16; off; off >>= 1) {
            acc0 += __shfl_xor_sync(0xffffffffu, acc0, off);
            acc1 += __shfl_xor_sync(0xffffffffu, acc1, off);
            acc2 += __shfl_xor_sync(0xffffffffu, acc2, off);
            acc3 += __shfl_xor_sync(0xffffffffu, acc3, off);
        }
        if (lane == 0) {
            s_sc[0][k] = acc0 + batt;
            s_sc[1][k] = acc1 + batt;
            s_sc[2][k] = acc2 + batt;
            s_sc[3][k] = acc3 + batt;
        }
    }
    __syncthreads();

    // 3) softmax per row (warps 0-3)
    if (wid < 4) {
        float* row = s_sc[wid];
        float m = -1e30f;
        for (int k = lane; k < TKL; k += 32) m = fmaxf(m, row[k]);
#pragma unroll
        for (int off = 16; off; off >>= 1) m = fmaxf(m, __shfl_xor_sync(0xffffffffu, m, off));
        float s = 0.f;
        for (int k = lane; k < TKL; k += 32) {
            float e = __expf(row[k] - m);
            row[k] = e;
            s += e;
        }
#pragma unroll
        for (int off = 16; off; off >>= 1) s += __shfl_xor_sync(0xffffffffu, s, off);
        const float inv = 1.0f / s;
        for (int k = lane; k < TKL; k += 32) row[k] *= inv;
    }
    __syncthreads();

    // 4) vectorized probs write (4 rows x 128 float4)
#pragma unroll
    for (int e = 0; e < 2; e++) {
        const int f = tid + 256 * e;
        const int q = f >> 7, ng = f & 127;
        *(float4*)(probs + (size_t)(b * TQL + q0 + q) * TKL + ng * 4) =
            *(const float4*)&s_sc[q][ng * 4];
    }
}

// ----------------------------------------------------------------------------
// MEGA: blocks [0,128) = scores+softmax (MUFU-bound, full rows);
//       blocks [128,384) = out-GEMM query-half (FFMA-bound).
// ----------------------------------------------------------------------------
__global__ __launch_bounds__(256) void mega_scores_qgemm(
    const float* __restrict__ keys,
    const float* __restrict__ w_att,
    const float* __restrict__ b_att,
    const float* __restrict__ b_q,
    const float* __restrict__ query,
    const float* __restrict__ W_out,
    float* __restrict__ probs)
{
    if (blockIdx.x < 128) {
        scores_softmax_body(keys, w_att, b_att, b_q, probs, blockIdx.x);
    } else {
        const int g = blockIdx.x - 128;      // 256 = 8n x 8m x 4z
        gemm_body<4>(query, W_out, 1024, 0, g_part2, 0,
                     g & 7, (g >> 3) & 7, g >> 6);
    }
}

// ----------------------------------------------------------------------------
// Standalone GEMM kernels
// ----------------------------------------------------------------------------
__global__ __launch_bounds__(256, 3) void gemm_attq(
    const float* __restrict__ query, const float* __restrict__ W_q)
{
    gemm_body<8>(query, W_q, 512, 0, g_part, 0, blockIdx.x, blockIdx.y, blockIdx.z);
}

__global__ __launch_bounds__(256, 3) void gemm_out_chalf(const float* __restrict__ W_out)
{
    gemm_body<4>(g_ctx, W_out, 1024, 512, g_part2, 4, blockIdx.x, blockIdx.y, blockIdx.z);
}

// ----------------------------------------------------------------------------
// Split-K NN GEMM for context: part[z][m][n] = sum_k P[m,k] * V_b[k,n]
// ----------------------------------------------------------------------------
template <int SPLITS>
__global__ __launch_bounds__(256, 3) void gemm_ctx_splitk(
    const float* __restrict__ P,
    const float* __restrict__ values)
{
    constexpr int CHUNK  = TKL / SPLITS;
    constexpr int STAGES = CHUNK / 16;

    __shared__ float As[2][16][68];
    __shared__ float Bs[2][16][68];

    const int tid = threadIdx.x;
    const int r   = tid >> 2;
    const int c   = tid & 3;
    const int bk  = tid >> 4;
    const int bn  = (tid & 15) * 4;
    const int ty  = tid >> 4;
    const int tx  = tid & 15;
    const int m0  = blockIdx.y * 64;
    const int n0  = blockIdx.x * 64;
    const int kst = blockIdx.z * CHUNK;

    const float* valb = values + (size_t)(m0 >> 7) * TKL * ND;

    float acc[4][4] = {};

    {
        float4 av = *(const float4*)(P + (size_t)(m0 + r) * TKL + kst + 4 * c);
        float4 bvv = *(const float4*)(valb + (size_t)(kst + bk) * ND + n0 + bn);
        float a4[4] = {av.x, av.y, av.z, av.w};
#pragma unroll
        for (int j = 0; j < 4; j++) As[0][4 * c + j][r] = a4[j];
        *(float4*)&Bs[0][bk][bn] = bvv;
    }
    __syncthreads();

    int buf = 0;
#pragma unroll 1
    for (int s = 0; s < STAGES; s++) {
        float4 anx, bnx;
        if (s + 1 < STAGES) {
            const int kb = kst + (s + 1) * 16;
            anx = *(const float4*)(P + (size_t)(m0 + r) * TKL + kb + 4 * c);
            bnx = *(const float4*)(valb + (size_t)(kb + bk) * ND + n0 + bn);
        }

        float4 a_c = *(const float4*)&As[buf][0][ty * 4];
        float4 b_c = *(const float4*)&Bs[buf][0][tx * 4];
#pragma unroll
        for (int kk = 0; kk < 16; kk++) {
            float4 a_n, b_n;
            if (kk < 15) {
                a_n = *(const float4*)&As[buf][kk + 1][ty * 4];
                b_n = *(const float4*)&Bs[buf][kk + 1][tx * 4];
            }
            float a4[4] = {a_c.x, a_c.y, a_c.z, a_c.w};
            float b4[4] = {b_c.x, b_c.y, b_c.z, b_c.w};
#pragma unroll
            for (int i = 0; i < 4; i++)
#pragma unroll
                for (int j = 0; j < 4; j++)
                    acc[i][j] += a4[i] * b4[j];
            if (kk < 15) { a_c = a_n; b_c = b_n; }
        }

        if (s + 1 < STAGES) {
            const int nb = buf ^ 1;
            float a4[4] = {anx.x, anx.y, anx.z, anx.w};
#pragma unroll
            for (int j = 0; j < 4; j++) As[nb][4 * c + j][r] = a4[j];
            *(float4*)&Bs[nb][bk][bn] = bnx;
            __syncthreads();
            buf = nb;
        }
    }

    float* pp = g_part + (size_t)blockIdx.z * SLAB;
#pragma unroll
    for (int i = 0; i < 4; i++) {
        float4 v = make_float4(acc[i][0], acc[i][1], acc[i][2], acc[i][3]);
        *(float4*)&pp[(size_t)(m0 + ty * 4 + i) * 512 + n0 + tx * 4] = v;
    }
}

// ----------------------------------------------------------------------------
// Reductions (512 blocks x 128 threads for latency coverage)
// ----------------------------------------------------------------------------
__global__ __launch_bounds__(128) void reduce_ctx_k()
{
    const int idx = blockIdx.x * 128 + threadIdx.x;
    const float4* p = (const float4*)g_part;
    float4 s = p[idx];
#pragma unroll
    for (int sp = 1; sp < 8; sp++) {
        float4 t = p[(size_t)sp * (SLAB / 4) + idx];
        s.x += t.x; s.y += t.y; s.z += t.z; s.w += t.w;
    }
    ((float4*)g_ctx)[idx] = s;
}

__global__ __launch_bounds__(128) void reduce_out_k(
    const float* __restrict__ bias, float* __restrict__ dext)
{
    const int idx = blockIdx.x * 128 + threadIdx.x;
    const float4* p = (const float4*)g_part2;
    float4 s = p[idx];
#pragma unroll
    for (int sp = 1; sp < 8; sp++) {
        float4 t = p[(size_t)sp * (SLAB / 4) + idx];
        s.x += t.x; s.y += t.y; s.z += t.z; s.w += t.w;
    }
    const float4 bb = ((const float4*)bias)[idx & (512 / 4 - 1)];
    s.x = tanhf(s.x + bb.x); s.y = tanhf(s.y + bb.y);
    s.z = tanhf(s.z + bb.z); s.w = tanhf(s.w + bb.w);
    ((float4*)dext)[idx] = s;
}

// ----------------------------------------------------------------------------
// Launch sequence (graph-capturable, allocation-free):
//   1) gemm_attq:  query @ W_q^T partials              -> g_part[0..7]
//   2) MEGA:       scores+softmax (fused attq reduce)  -> probs (output)
//                  || out-GEMM query-half              -> g_part2[0..3]
//   3) gemm_ctx:   probs @ values partials             -> g_part[0..7]
//   4) reduce_ctx                                      -> g_ctx
//   5) out-GEMM ctx-half                               -> g_part2[4..7]
//   6) reduce_out: sum + b_out + tanh                  -> out (output)
// ----------------------------------------------------------------------------
extern "C" void kernel_launch(void* const* d_in, const int* in_sizes, int n_in,
                              void* d_out, int out_size)
{
    const float* query  = (const float*)d_in[0];
    const float* keys   = (const float*)d_in[1];
    const float* values = (const float*)d_in[2];
    const float* W_q    = (const float*)d_in[3];
    const float* b_q    = (const float*)d_in[4];
    const float* w_att  = (const float*)d_in[5];
    const float* b_att  = (const float*)d_in[6];
    const float* W_out  = (const float*)d_in[7];
    const float* b_out  = (const float*)d_in[8];

    float* out   = (float*)d_out;
    float* probs = out + (size_t)MROWS * OD;

    gemm_attq<<<dim3(8, 8, 8), 256>>>(query, W_q);

    mega_scores_qgemm<<<384, 256>>>(keys, w_att, b_att, b_q, query, W_out, probs);

    gemm_ctx_splitk<8><<<dim3(8, 8, 8), 256>>>(probs, values);
    reduce_ctx_k<<<512, 128>>>();

    gemm_out_chalf<<<dim3(8, 8, 4), 256>>>(W_out);
    reduce_out_k<<<512, 128>>>(b_out, out);
}

// round 14
// speedup vs baseline: 1.0775x; 1.0775x over previous
#include <cuda_runtime.h>
#include <math.h>

#define BATCH 4
#define TQL   128
#define TKL   512
#define ND    512
#define OD    512
#define MROWS (BATCH * TQL)     // 512
#define SLAB  (MROWS * 512)     // one partial slab

// Scratch (device globals -- no allocation allowed)
__device__ __align__(16) float g_ctx  [MROWS * ND];
__device__ __align__(16) float g_part [8 * SLAB];   // attq partials, then ctx partials
__device__ __align__(16) float g_part2[8 * SLAB];   // out-GEMM partials (qhalf 0-3, chalf 4-7)

__device__ __forceinline__ float fast_tanh(float x) {
    float y;
    asm("tanh.approx.f32 %0, %1;" : "=f"(y) : "f"(x));
    return y;
}

// ----------------------------------------------------------------------------
// Split-K NT GEMM body over a K=512 range (R12 version, NO register pipeline):
//   part[z0+bz][m][n] = sum_{k in chunk bz} A0[m,k] * B[n, boff+k]
// ----------------------------------------------------------------------------
template <int SPLITS>
__device__ __forceinline__ void gemm_body(
    const float* __restrict__ A0, const float* __restrict__ B,
    int bstride, int boff, float* __restrict__ part, int z0,
    int bx, int by, int bz)
{
    constexpr int CHUNK  = 512 / SPLITS;
    constexpr int STAGES = CHUNK / 16;

    __shared__ float As[2][16][68];
    __shared__ float Bs[2][16][68];

    const int tid = threadIdx.x;
    const int r   = tid >> 2;
    const int c   = tid & 3;
    const int ty  = tid >> 4;
    const int tx  = tid & 15;
    const int m0  = by * 64;
    const int n0  = bx * 64;
    const int kst = bz * CHUNK;

    float acc[4][4] = {};

    {
        float4 av = *(const float4*)(A0 + (size_t)(m0 + r) * 512 + kst + 4 * c);
        float4 bv = *(const float4*)(B + (size_t)(n0 + r) * bstride + boff + kst + 4 * c);
        float a4[4] = {av.x, av.y, av.z, av.w};
        float b4[4] = {bv.x, bv.y, bv.z, bv.w};
#pragma unroll
        for (int j = 0; j < 4; j++) {
            As[0][4 * c + j][r] = a4[j];
            Bs[0][4 * c + j][r] = b4[j];
        }
    }
    __syncthreads();

    int buf = 0;
#pragma unroll 1
    for (int s = 0; s < STAGES; s++) {
        float4 anx, bnx;
        if (s + 1 < STAGES) {
            const int kb = kst + (s + 1) * 16;
            anx = *(const float4*)(A0 + (size_t)(m0 + r) * 512 + kb + 4 * c);
            bnx = *(const float4*)(B + (size_t)(n0 + r) * bstride + boff + kb + 4 * c);
        }

#pragma unroll
        for (int kk = 0; kk < 16; kk++) {
            float4 a = *(const float4*)&As[buf][kk][ty * 4];
            float4 b = *(const float4*)&Bs[buf][kk][tx * 4];
            float a4[4] = {a.x, a.y, a.z, a.w};
            float b4[4] = {b.x, b.y, b.z, b.w};
#pragma unroll
            for (int i = 0; i < 4; i++)
#pragma unroll
                for (int j = 0; j < 4; j++)
                    acc[i][j] += a4[i] * b4[j];
        }

        if (s + 1 < STAGES) {
            const int nb = buf ^ 1;
            float a4[4] = {anx.x, anx.y, anx.z, anx.w};
            float b4[4] = {bnx.x, bnx.y, bnx.z, bnx.w};
#pragma unroll
            for (int j = 0; j < 4; j++) {
                As[nb][4 * c + j][r] = a4[j];
                Bs[nb][4 * c + j][r] = b4[j];
            }
            __syncthreads();
            buf = nb;
        }
    }

    float* pp = part + (size_t)(z0 + bz) * SLAB;
#pragma unroll
    for (int i = 0; i < 4; i++) {
        float4 v = make_float4(acc[i][0], acc[i][1], acc[i][2], acc[i][3]);
        *(float4*)&pp[(size_t)(m0 + ty * 4 + i) * 512 + n0 + tx * 4] = v;
    }
}

// ----------------------------------------------------------------------------
// Scores + fused softmax body: block owns 2 FULL query rows (all 512 keys).
// 256 such blocks keep the whole chip covered (vs R13's 128-block mistake).
// 1) fused split-K reduce of att_query (2 rows) + b_q into smem
// 2) scores for 2 q x 512 k (MUFU tanh bound) into smem
// 3) per-row softmax (warps 0-1)
// 4) vectorized probs write
// ----------------------------------------------------------------------------
__device__ __forceinline__ void scores_softmax_body(
    const float* __restrict__ keys,
    const float* __restrict__ w_att,
    const float* __restrict__ b_att,
    const float* __restrict__ b_q,
    float* __restrict__ probs,
    int bi)
{
    __shared__ float s_aq[2][512];   // 4 KB
    __shared__ float s_sc[2][512];   // 4 KB

    const int tid  = threadIdx.x;
    const int wid  = tid >> 5;
    const int lane = tid & 31;
    const int q0   = (bi & 63) << 1;     // 2 queries per block
    const int b    = bi >> 6;

    // 1) fused split-K reduce of att_query (2 rows x 128 float4 = 256 float4)
    {
        const int q  = tid >> 7, ng = tid & 127;
        const size_t row4 = ((size_t)(b * TQL + q0 + q) * 512) / 4 + ng;
        float4 s = ((const float4*)b_q)[ng];
#pragma unroll
        for (int sp = 0; sp < 8; sp++) {
            float4 t = ((const float4*)g_part)[(size_t)sp * (SLAB / 4) + row4];
            s.x += t.x; s.y += t.y; s.z += t.z; s.w += t.w;
        }
        *(float4*)&s_aq[q][ng * 4] = s;
    }
    __syncthreads();

    // 2) register-resident w_att + att_query (lane owns 16 n-positions)
    float wreg[16];
    float areg[2][16];
#pragma unroll
    for (int i = 0; i < 4; i++) {
        float4 w4 = *(const float4*)(w_att + i * 128 + lane * 4);
        wreg[i * 4 + 0] = w4.x; wreg[i * 4 + 1] = w4.y;
        wreg[i * 4 + 2] = w4.z; wreg[i * 4 + 3] = w4.w;
#pragma unroll
        for (int q = 0; q < 2; q++) {
            float4 a4 = *(const float4*)&s_aq[q][i * 128 + lane * 4];
            areg[q][i * 4 + 0] = a4.x; areg[q][i * 4 + 1] = a4.y;
            areg[q][i * 4 + 2] = a4.z; areg[q][i * 4 + 3] = a4.w;
        }
    }
    const float batt = b_att[0];
    const float* keyb = keys + (size_t)b * TKL * ND;

    for (int k = wid; k < TKL; k += 8) {
        const float* kr = keyb + (size_t)k * ND;
        float acc0 = 0.f, acc1 = 0.f;
#pragma unroll
        for (int i = 0; i < 4; i++) {
            float4 k4 = *(const float4*)(kr + i * 128 + lane * 4);
            float kv[4] = {k4.x, k4.y, k4.z, k4.w};
#pragma unroll
            for (int j = 0; j < 4; j++) {
                const float w = wreg[i * 4 + j];
                acc0 += w * fast_tanh(areg[0][i * 4 + j] + kv[j]);
                acc1 += w * fast_tanh(areg[1][i * 4 + j] + kv[j]);
            }
        }
#pragma unroll
        for (int off = 16; off; off >>= 1) {
            acc0 += __shfl_xor_sync(0xffffffffu, acc0, off);
            acc1 += __shfl_xor_sync(0xffffffffu, acc1, off);
        }
        if (lane == 0) {
            s_sc[0][k] = acc0 + batt;
            s_sc[1][k] = acc1 + batt;
        }
    }
    __syncthreads();

    // 3) softmax per row (warps 0-1), register-resident 16 floats/lane
    if (wid < 2) {
        float* row = s_sc[wid];
        float v[16];
        float m = -1e30f;
#pragma unroll
        for (int i = 0; i < 4; i++) {
            float4 t = *(const float4*)&row[i * 128 + lane * 4];
            v[i * 4 + 0] = t.x; v[i * 4 + 1] = t.y;
            v[i * 4 + 2] = t.z; v[i * 4 + 3] = t.w;
            m = fmaxf(m, fmaxf(fmaxf(t.x, t.y), fmaxf(t.z, t.w)));
        }
#pragma unroll
        for (int off = 16; off; off >>= 1) m = fmaxf(m, __shfl_xor_sync(0xffffffffu, m, off));
        float s = 0.f;
#pragma unroll
        for (int i = 0; i < 16; i++) {
            v[i] = __expf(v[i] - m);
            s += v[i];
        }
#pragma unroll
        for (int off = 16; off; off >>= 1) s += __shfl_xor_sync(0xffffffffu, s, off);
        const float inv = 1.0f / s;
#pragma unroll
        for (int i = 0; i < 4; i++) {
            float4 t = make_float4(v[i * 4 + 0] * inv, v[i * 4 + 1] * inv,
                                   v[i * 4 + 2] * inv, v[i * 4 + 3] * inv);
            *(float4*)&row[i * 128 + lane * 4] = t;
        }
    }
    __syncthreads();

    // 4) vectorized probs write (2 rows x 128 float4 = 256 float4)
    {
        const int q = tid >> 7, ng = tid & 127;
        *(float4*)(probs + (size_t)(b * TQL + q0 + q) * TKL + ng * 4) =
            *(const float4*)&s_sc[q][ng * 4];
    }
}

// ----------------------------------------------------------------------------
// MEGA: blocks [0,256) = scores+softmax (MUFU-bound, 2 full rows each);
//       blocks [256,512) = out-GEMM query-half (FFMA-bound).
// ----------------------------------------------------------------------------
__global__ __launch_bounds__(256) void mega_scores_qgemm(
    const float* __restrict__ keys,
    const float* __restrict__ w_att,
    const float* __restrict__ b_att,
    const float* __restrict__ b_q,
    const float* __restrict__ query,
    const float* __restrict__ W_out,
    float* __restrict__ probs)
{
    if (blockIdx.x < 256) {
        scores_softmax_body(keys, w_att, b_att, b_q, probs, blockIdx.x);
    } else {
        const int g = blockIdx.x - 256;      // 256 = 8n x 8m x 4z
        gemm_body<4>(query, W_out, 1024, 0, g_part2, 0,
                     g & 7, (g >> 3) & 7, g >> 6);
    }
}

// ----------------------------------------------------------------------------
// Standalone GEMM kernels
// ----------------------------------------------------------------------------
__global__ __launch_bounds__(256, 3) void gemm_attq(
    const float* __restrict__ query, const float* __restrict__ W_q)
{
    gemm_body<8>(query, W_q, 512, 0, g_part, 0, blockIdx.x, blockIdx.y, blockIdx.z);
}

__global__ __launch_bounds__(256, 3) void gemm_out_chalf(const float* __restrict__ W_out)
{
    gemm_body<4>(g_ctx, W_out, 1024, 512, g_part2, 4, blockIdx.x, blockIdx.y, blockIdx.z);
}

// ----------------------------------------------------------------------------
// Split-K NN GEMM for context: part[z][m][n] = sum_k P[m,k] * V_b[k,n]
// (R12 version, NO register pipeline)
// ----------------------------------------------------------------------------
template <int SPLITS>
__global__ __launch_bounds__(256, 3) void gemm_ctx_splitk(
    const float* __restrict__ P,
    const float* __restrict__ values)
{
    constexpr int CHUNK  = TKL / SPLITS;
    constexpr int STAGES = CHUNK / 16;

    __shared__ float As[2][16][68];
    __shared__ float Bs[2][16][68];

    const int tid = threadIdx.x;
    const int r   = tid >> 2;
    const int c   = tid & 3;
    const int bk  = tid >> 4;
    const int bn  = (tid & 15) * 4;
    const int ty  = tid >> 4;
    const int tx  = tid & 15;
    const int m0  = blockIdx.y * 64;
    const int n0  = blockIdx.x * 64;
    const int kst = blockIdx.z * CHUNK;

    const float* valb = values + (size_t)(m0 >> 7) * TKL * ND;

    float acc[4][4] = {};

    {
        float4 av = *(const float4*)(P + (size_t)(m0 + r) * TKL + kst + 4 * c);
        float4 bvv = *(const float4*)(valb + (size_t)(kst + bk) * ND + n0 + bn);
        float a4[4] = {av.x, av.y, av.z, av.w};
#pragma unroll
        for (int j = 0; j < 4; j++) As[0][4 * c + j][r] = a4[j];
        *(float4*)&Bs[0][bk][bn] = bvv;
    }
    __syncthreads();

    int buf = 0;
#pragma unroll 1
    for (int s = 0; s < STAGES; s++) {
        float4 anx, bnx;
        if (s + 1 < STAGES) {
            const int kb = kst + (s + 1) * 16;
            anx = *(const float4*)(P + (size_t)(m0 + r) * TKL + kb + 4 * c);
            bnx = *(const float4*)(valb + (size_t)(kb + bk) * ND + n0 + bn);
        }

#pragma unroll
        for (int kk = 0; kk < 16; kk++) {
            float4 a = *(const float4*)&As[buf][kk][ty * 4];
            float4 b = *(const float4*)&Bs[buf][kk][tx * 4];
            float a4[4] = {a.x, a.y, a.z, a.w};
            float b4[4] = {b.x, b.y, b.z, b.w};
#pragma unroll
            for (int i = 0; i < 4; i++)
#pragma unroll
                for (int j = 0; j < 4; j++)
                    acc[i][j] += a4[i] * b4[j];
        }

        if (s + 1 < STAGES) {
            const int nb = buf ^ 1;
            float a4[4] = {anx.x, anx.y, anx.z, anx.w};
#pragma unroll
            for (int j = 0; j < 4; j++) As[nb][4 * c + j][r] = a4[j];
            *(float4*)&Bs[nb][bk][bn] = bnx;
            __syncthreads();
            buf = nb;
        }
    }

    float* pp = g_part + (size_t)blockIdx.z * SLAB;
#pragma unroll
    for (int i = 0; i < 4; i++) {
        float4 v = make_float4(acc[i][0], acc[i][1], acc[i][2], acc[i][3]);
        *(float4*)&pp[(size_t)(m0 + ty * 4 + i) * 512 + n0 + tx * 4] = v;
    }
}

// ----------------------------------------------------------------------------
// Reductions (R12 shape: 256 blocks x 256 threads)
// ----------------------------------------------------------------------------
__global__ __launch_bounds__(256) void reduce_ctx_k()
{
    const int idx = blockIdx.x * 256 + threadIdx.x;
    const float4* p = (const float4*)g_part;
    float4 s = p[idx];
#pragma unroll
    for (int sp = 1; sp < 8; sp++) {
        float4 t = p[(size_t)sp * (SLAB / 4) + idx];
        s.x += t.x; s.y += t.y; s.z += t.z; s.w += t.w;
    }
    ((float4*)g_ctx)[idx] = s;
}

__global__ __launch_bounds__(256) void reduce_out_k(
    const float* __restrict__ bias, float* __restrict__ dext)
{
    const int idx = blockIdx.x * 256 + threadIdx.x;
    const float4* p = (const float4*)g_part2;
    float4 s = p[idx];
#pragma unroll
    for (int sp = 1; sp < 8; sp++) {
        float4 t = p[(size_t)sp * (SLAB / 4) + idx];
        s.x += t.x; s.y += t.y; s.z += t.z; s.w += t.w;
    }
    const float4 bb = ((const float4*)bias)[idx & (512 / 4 - 1)];
    s.x = tanhf(s.x + bb.x); s.y = tanhf(s.y + bb.y);
    s.z = tanhf(s.z + bb.z); s.w = tanhf(s.w + bb.w);
    ((float4*)dext)[idx] = s;
}

// ----------------------------------------------------------------------------
// Launch sequence (graph-capturable, allocation-free):
//   1) gemm_attq:  query @ W_q^T partials               -> g_part[0..7]
//   2) MEGA:       scores + fused softmax               -> probs (output)
//                  || out-GEMM query-half               -> g_part2[0..3]
//   3) gemm_ctx:   probs @ values partials              -> g_part[0..7]
//   4) reduce_ctx                                       -> g_ctx
//   5) out-GEMM ctx-half                                -> g_part2[4..7]
//   6) reduce_out: sum + b_out + tanh                   -> out (output)
// ----------------------------------------------------------------------------
extern "C" void kernel_launch(void* const* d_in, const int* in_sizes, int n_in,
                              void* d_out, int out_size)
{
    const float* query  = (const float*)d_in[0];
    const float* keys   = (const float*)d_in[1];
    const float* values = (const float*)d_in[2];
    const float* W_q    = (const float*)d_in[3];
    const float* b_q    = (const float*)d_in[4];
    const float* w_att  = (const float*)d_in[5];
    const float* b_att  = (const float*)d_in[6];
    const float* W_out  = (const float*)d_in[7];
    const float* b_out  = (const float*)d_in[8];

    float* out   = (float*)d_out;
    float* probs = out + (size_t)MROWS * OD;

    gemm_attq<<<dim3(8, 8, 8), 256>>>(query, W_q);

    mega_scores_qgemm<<<512, 256>>>(keys, w_att, b_att, b_q, query, W_out, probs);

    gemm_ctx_splitk<8><<<dim3(8, 8, 8), 256>>>(probs, values);
    reduce_ctx_k<<<256, 256>>>();

    gemm_out_chalf<<<dim3(8, 8, 4), 256>>>(W_out);
    reduce_out_k<<<256, 256>>>(b_out, out);
}

// round 15
// speedup vs baseline: 1.3990x; 1.2984x over previous
#include <cuda_runtime.h>
#include <math.h>

#define BATCH 4
#define TQL   128
#define TKL   512
#define ND    512
#define OD    512
#define MROWS (BATCH * TQL)     // 512
#define SLAB  (MROWS * 512)     // one partial slab

// Scratch (device globals -- no allocation allowed)
__device__ __align__(16) float g_ctx   [MROWS * ND];
__device__ __align__(16) float g_scores[MROWS * TKL];   // exp(score) (unnormalized)
__device__ __align__(16) float g_ssum  [MROWS * 2];     // per-row half-sums of exp
__device__ __align__(16) float g_part  [8 * SLAB];      // attq partials, then ctx partials
__device__ __align__(16) float g_part2 [8 * SLAB];      // out-GEMM partials (qhalf 0-3, chalf 4-7)

__device__ __forceinline__ float fast_tanh(float x) {
    float y;
    asm("tanh.approx.f32 %0, %1;" : "=f"(y) : "f"(x));
    return y;
}

// ----------------------------------------------------------------------------
// Split-K NT GEMM body over a K=512 range (R12 version):
//   part[z0+bz][m][n] = sum_{k in chunk bz} A0[m,k] * B[n, boff+k]
// ----------------------------------------------------------------------------
template <int SPLITS>
__device__ __forceinline__ void gemm_body(
    const float* __restrict__ A0, const float* __restrict__ B,
    int bstride, int boff, float* __restrict__ part, int z0,
    int bx, int by, int bz)
{
    constexpr int CHUNK  = 512 / SPLITS;
    constexpr int STAGES = CHUNK / 16;

    __shared__ float As[2][16][68];
    __shared__ float Bs[2][16][68];

    const int tid = threadIdx.x;
    const int r   = tid >> 2;
    const int c   = tid & 3;
    const int ty  = tid >> 4;
    const int tx  = tid & 15;
    const int m0  = by * 64;
    const int n0  = bx * 64;
    const int kst = bz * CHUNK;

    float acc[4][4] = {};

    {
        float4 av = *(const float4*)(A0 + (size_t)(m0 + r) * 512 + kst + 4 * c);
        float4 bv = *(const float4*)(B + (size_t)(n0 + r) * bstride + boff + kst + 4 * c);
        float a4[4] = {av.x, av.y, av.z, av.w};
        float b4[4] = {bv.x, bv.y, bv.z, bv.w};
#pragma unroll
        for (int j = 0; j < 4; j++) {
            As[0][4 * c + j][r] = a4[j];
            Bs[0][4 * c + j][r] = b4[j];
        }
    }
    __syncthreads();

    int buf = 0;
#pragma unroll 1
    for (int s = 0; s < STAGES; s++) {
        float4 anx, bnx;
        if (s + 1 < STAGES) {
            const int kb = kst + (s + 1) * 16;
            anx = *(const float4*)(A0 + (size_t)(m0 + r) * 512 + kb + 4 * c);
            bnx = *(const float4*)(B + (size_t)(n0 + r) * bstride + boff + kb + 4 * c);
        }

#pragma unroll
        for (int kk = 0; kk < 16; kk++) {
            float4 a = *(const float4*)&As[buf][kk][ty * 4];
            float4 b = *(const float4*)&Bs[buf][kk][tx * 4];
            float a4[4] = {a.x, a.y, a.z, a.w};
            float b4[4] = {b.x, b.y, b.z, b.w};
#pragma unroll
            for (int i = 0; i < 4; i++)
#pragma unroll
                for (int j = 0; j < 4; j++)
                    acc[i][j] += a4[i] * b4[j];
        }

        if (s + 1 < STAGES) {
            const int nb = buf ^ 1;
            float a4[4] = {anx.x, anx.y, anx.z, anx.w};
            float b4[4] = {bnx.x, bnx.y, bnx.z, bnx.w};
#pragma unroll
            for (int j = 0; j < 4; j++) {
                As[nb][4 * c + j][r] = a4[j];
                Bs[nb][4 * c + j][r] = b4[j];
            }
            __syncthreads();
            buf = nb;
        }
    }

    float* pp = part + (size_t)(z0 + bz) * SLAB;
#pragma unroll
    for (int i = 0; i < 4; i++) {
        float4 v = make_float4(acc[i][0], acc[i][1], acc[i][2], acc[i][3]);
        *(float4*)&pp[(size_t)(m0 + ty * 4 + i) * 512 + n0 + tx * 4] = v;
    }
}

// ----------------------------------------------------------------------------
// Scores body (R12 shape: 4 queries x 256 keys per block) with fused attq
// reduce AND max-free exp: writes exp(score) to g_scores and per-row-half
// sums to g_ssum. (Scores bounded by sum|w_att| ~ 8.3 -> exp is fp32-safe.)
// ----------------------------------------------------------------------------
__device__ __forceinline__ void scores_body(
    const float* __restrict__ keys,
    const float* __restrict__ w_att,
    const float* __restrict__ b_att,
    const float* __restrict__ b_q,
    int bi)
{
    __shared__ float s_aq[4][512];   // 8 KB
    __shared__ float s_sc[4][256];   // 4 KB (exp scores, this key-half)

    const int tid  = threadIdx.x;
    const int wid  = tid >> 5;
    const int lane = tid & 31;
    const int kh   = bi & 1;
    const int q0   = ((bi >> 1) & 31) << 2;
    const int b    = bi >> 6;

    // 1) fused split-K reduce of att_query (vectorized)
#pragma unroll
    for (int e = 0; e < 2; e++) {
        const int f  = tid + 256 * e;      // float4 index 0..511
        const int q  = f >> 7, ng = f & 127;
        const size_t row4 = ((size_t)(b * TQL + q0 + q) * 512) / 4 + ng;
        float4 s = ((const float4*)b_q)[ng];
#pragma unroll
        for (int sp = 0; sp < 8; sp++) {
            float4 t = ((const float4*)g_part)[(size_t)sp * (SLAB / 4) + row4];
            s.x += t.x; s.y += t.y; s.z += t.z; s.w += t.w;
        }
        *(float4*)&s_aq[q][ng * 4] = s;
    }
    __syncthreads();

    // 2) register-resident w_att + att_query (lane owns 16 n-positions)
    float wreg[16];
    float areg[4][16];
#pragma unroll
    for (int i = 0; i < 4; i++) {
        float4 w4 = *(const float4*)(w_att + i * 128 + lane * 4);
        wreg[i * 4 + 0] = w4.x; wreg[i * 4 + 1] = w4.y;
        wreg[i * 4 + 2] = w4.z; wreg[i * 4 + 3] = w4.w;
#pragma unroll
        for (int q = 0; q < 4; q++) {
            float4 a4 = *(const float4*)&s_aq[q][i * 128 + lane * 4];
            areg[q][i * 4 + 0] = a4.x; areg[q][i * 4 + 1] = a4.y;
            areg[q][i * 4 + 2] = a4.z; areg[q][i * 4 + 3] = a4.w;
        }
    }
    const float batt = b_att[0];
    const float* keyb = keys + (size_t)b * TKL * ND;
    float* sco = g_scores + (size_t)(b * TQL + q0) * TKL;

    // 3) scores + exp (MUFU tanh bound)
    const int kend = kh * 256 + 256;
    for (int k = kh * 256 + wid; k < kend; k += 8) {
        const float* kr = keyb + (size_t)k * ND;
        float acc0 = 0.f, acc1 = 0.f, acc2 = 0.f, acc3 = 0.f;
#pragma unroll
        for (int i = 0; i < 4; i++) {
            float4 k4 = *(const float4*)(kr + i * 128 + lane * 4);
            float kv[4] = {k4.x, k4.y, k4.z, k4.w};
#pragma unroll
            for (int j = 0; j < 4; j++) {
                const float w = wreg[i * 4 + j];
                acc0 += w * fast_tanh(areg[0][i * 4 + j] + kv[j]);
                acc1 += w * fast_tanh(areg[1][i * 4 + j] + kv[j]);
                acc2 += w * fast_tanh(areg[2][i * 4 + j] + kv[j]);
                acc3 += w * fast_tanh(areg[3][i * 4 + j] + kv[j]);
            }
        }
#pragma unroll
        for (int off = 16; off; off >>= 1) {
            acc0 += __shfl_xor_sync(0xffffffffu, acc0, off);
            acc1 += __shfl_xor_sync(0xffffffffu, acc1, off);
            acc2 += __shfl_xor_sync(0xffffffffu, acc2, off);
            acc3 += __shfl_xor_sync(0xffffffffu, acc3, off);
        }
        if (lane == 0) {
            const int kl = k - kh * 256;
            float e0 = __expf(acc0 + batt);
            float e1 = __expf(acc1 + batt);
            float e2 = __expf(acc2 + batt);
            float e3 = __expf(acc3 + batt);
            s_sc[0][kl] = e0; sco[0 * TKL + k] = e0;
            s_sc[1][kl] = e1; sco[1 * TKL + k] = e1;
            s_sc[2][kl] = e2; sco[2 * TKL + k] = e2;
            s_sc[3][kl] = e3; sco[3 * TKL + k] = e3;
        }
    }
    __syncthreads();

    // 4) per-row-half exp sums (warps 0-3, one row each)
    if (wid < 4) {
        float s = 0.f;
#pragma unroll
        for (int i = 0; i < 8; i++) s += s_sc[wid][lane + 32 * i];
#pragma unroll
        for (int off = 16; off; off >>= 1) s += __shfl_xor_sync(0xffffffffu, s, off);
        if (lane == 0)
            g_ssum[(size_t)(b * TQL + q0 + wid) * 2 + kh] = s;
    }
}

// ----------------------------------------------------------------------------
// MEGA: blocks [0,256) = scores+exp (MUFU-bound);
//       blocks [256,512) = out-GEMM query-half (FFMA-bound).
// ----------------------------------------------------------------------------
__global__ __launch_bounds__(256) void mega_scores_qgemm(
    const float* __restrict__ keys,
    const float* __restrict__ w_att,
    const float* __restrict__ b_att,
    const float* __restrict__ b_q,
    const float* __restrict__ query,
    const float* __restrict__ W_out)
{
    if (blockIdx.x < 256) {
        scores_body(keys, w_att, b_att, b_q, blockIdx.x);
    } else {
        const int g = blockIdx.x - 256;      // 256 = 8n x 8m x 4z
        gemm_body<4>(query, W_out, 1024, 0, g_part2, 0,
                     g & 7, (g >> 3) & 7, g >> 6);
    }
}

// ----------------------------------------------------------------------------
// Standalone GEMM kernels
// ----------------------------------------------------------------------------
__global__ __launch_bounds__(256, 3) void gemm_attq(
    const float* __restrict__ query, const float* __restrict__ W_q)
{
    gemm_body<8>(query, W_q, 512, 0, g_part, 0, blockIdx.x, blockIdx.y, blockIdx.z);
}

__global__ __launch_bounds__(256, 3) void gemm_out_chalf(const float* __restrict__ W_out)
{
    gemm_body<4>(g_ctx, W_out, 1024, 512, g_part2, 4, blockIdx.x, blockIdx.y, blockIdx.z);
}

// ----------------------------------------------------------------------------
// Split-K NN GEMM for context with FUSED softmax normalization:
//   part[z][m][n] = sum_k (exp_sc[m,k] / rowsum[m]) * V_b[k,n]
// A-tiles are scaled by 1/rowsum at load; bx==0 blocks also write the
// normalized chunk to probs (the final softmax output) as a store-only side
// effect of loads they already perform.
// ----------------------------------------------------------------------------
template <int SPLITS>
__global__ __launch_bounds__(256, 3) void gemm_ctx_splitk(
    const float* __restrict__ values,
    float* __restrict__ probs)
{
    constexpr int CHUNK  = TKL / SPLITS;
    constexpr int STAGES = CHUNK / 16;

    __shared__ float As[2][16][68];
    __shared__ float Bs[2][16][68];

    const int tid = threadIdx.x;
    const int r   = tid >> 2;
    const int c   = tid & 3;
    const int bk  = tid >> 4;
    const int bn  = (tid & 15) * 4;
    const int ty  = tid >> 4;
    const int tx  = tid & 15;
    const int m0  = blockIdx.y * 64;
    const int n0  = blockIdx.x * 64;
    const int kst = blockIdx.z * CHUNK;
    const bool wp = (blockIdx.x == 0);

    const float* valb = values + (size_t)(m0 >> 7) * TKL * ND;
    const float* P = g_scores;

    // per-thread row scale (row fixed for this thread's A loads)
    const int mrow = m0 + r;
    const float inv = 1.0f / (g_ssum[2 * mrow] + g_ssum[2 * mrow + 1]);

    float acc[4][4] = {};

    {
        float4 av = *(const float4*)(P + (size_t)mrow * TKL + kst + 4 * c);
        float4 bvv = *(const float4*)(valb + (size_t)(kst + bk) * ND + n0 + bn);
        float a4[4] = {av.x * inv, av.y * inv, av.z * inv, av.w * inv};
#pragma unroll
        for (int j = 0; j < 4; j++) As[0][4 * c + j][r] = a4[j];
        if (wp)
            *(float4*)(probs + (size_t)mrow * TKL + kst + 4 * c) =
                make_float4(a4[0], a4[1], a4[2], a4[3]);
        *(float4*)&Bs[0][bk][bn] = bvv;
    }
    __syncthreads();

    int buf = 0;
#pragma unroll 1
    for (int s = 0; s < STAGES; s++) {
        float4 anx, bnx;
        if (s + 1 < STAGES) {
            const int kb = kst + (s + 1) * 16;
            anx = *(const float4*)(P + (size_t)mrow * TKL + kb + 4 * c);
            bnx = *(const float4*)(valb + (size_t)(kb + bk) * ND + n0 + bn);
        }

#pragma unroll
        for (int kk = 0; kk < 16; kk++) {
            float4 a = *(const float4*)&As[buf][kk][ty * 4];
            float4 b = *(const float4*)&Bs[buf][kk][tx * 4];
            float a4[4] = {a.x, a.y, a.z, a.w};
            float b4[4] = {b.x, b.y, b.z, b.w};
#pragma unroll
            for (int i = 0; i < 4; i++)
#pragma unroll
                for (int j = 0; j < 4; j++)
                    acc[i][j] += a4[i] * b4[j];
        }

        if (s + 1 < STAGES) {
            const int nb = buf ^ 1;
            const int kb = kst + (s + 1) * 16;
            float a4[4] = {anx.x * inv, anx.y * inv, anx.z * inv, anx.w * inv};
#pragma unroll
            for (int j = 0; j < 4; j++) As[nb][4 * c + j][r] = a4[j];
            if (wp)
                *(float4*)(probs + (size_t)mrow * TKL + kb + 4 * c) =
                    make_float4(a4[0], a4[1], a4[2], a4[3]);
            *(float4*)&Bs[nb][bk][bn] = bnx;
            __syncthreads();
            buf = nb;
        }
    }

    float* pp = g_part + (size_t)blockIdx.z * SLAB;
#pragma unroll
    for (int i = 0; i < 4; i++) {
        float4 v = make_float4(acc[i][0], acc[i][1], acc[i][2], acc[i][3]);
        *(float4*)&pp[(size_t)(m0 + ty * 4 + i) * 512 + n0 + tx * 4] = v;
    }
}

// ----------------------------------------------------------------------------
// Reductions (R12 shape: 256 blocks x 256 threads)
// ----------------------------------------------------------------------------
__global__ __launch_bounds__(256) void reduce_ctx_k()
{
    const int idx = blockIdx.x * 256 + threadIdx.x;
    const float4* p = (const float4*)g_part;
    float4 s = p[idx];
#pragma unroll
    for (int sp = 1; sp < 8; sp++) {
        float4 t = p[(size_t)sp * (SLAB / 4) + idx];
        s.x += t.x; s.y += t.y; s.z += t.z; s.w += t.w;
    }
    ((float4*)g_ctx)[idx] = s;
}

__global__ __launch_bounds__(256) void reduce_out_k(
    const float* __restrict__ bias, float* __restrict__ dext)
{
    const int idx = blockIdx.x * 256 + threadIdx.x;
    const float4* p = (const float4*)g_part2;
    float4 s = p[idx];
#pragma unroll
    for (int sp = 1; sp < 8; sp++) {
        float4 t = p[(size_t)sp * (SLAB / 4) + idx];
        s.x += t.x; s.y += t.y; s.z += t.z; s.w += t.w;
    }
    const float4 bb = ((const float4*)bias)[idx & (512 / 4 - 1)];
    s.x = tanhf(s.x + bb.x); s.y = tanhf(s.y + bb.y);
    s.z = tanhf(s.z + bb.z); s.w = tanhf(s.w + bb.w);
    ((float4*)dext)[idx] = s;
}

// ----------------------------------------------------------------------------
// Launch sequence (graph-capturable, allocation-free):
//   1) gemm_attq:  query @ W_q^T partials               -> g_part[0..7]
//   2) MEGA:       scores + exp + row-half sums         -> g_scores, g_ssum
//                  || out-GEMM query-half               -> g_part2[0..3]
//   3) gemm_ctx:   (exp/rowsum) @ values partials       -> g_part[0..7]
//                  (bx==0 blocks also emit probs output)
//   4) reduce_ctx                                       -> g_ctx
//   5) out-GEMM ctx-half                                -> g_part2[4..7]
//   6) reduce_out: sum + b_out + tanh                   -> out (output)
// ----------------------------------------------------------------------------
extern "C" void kernel_launch(void* const* d_in, const int* in_sizes, int n_in,
                              void* d_out, int out_size)
{
    const float* query  = (const float*)d_in[0];
    const float* keys   = (const float*)d_in[1];
    const float* values = (const float*)d_in[2];
    const float* W_q    = (const float*)d_in[3];
    const float* b_q    = (const float*)d_in[4];
    const float* w_att  = (const float*)d_in[5];
    const float* b_att  = (const float*)d_in[6];
    const float* W_out  = (const float*)d_in[7];
    const float* b_out  = (const float*)d_in[8];

    float* out   = (float*)d_out;
    float* probs = out + (size_t)MROWS * OD;

    gemm_attq<<<dim3(8, 8, 8), 256>>>(query, W_q);

    mega_scores_qgemm<<<512, 256>>>(keys, w_att, b_att, b_q, query, W_out);

    gemm_ctx_splitk<8><<<dim3(8, 8, 8), 256>>>(values, probs);
    reduce_ctx_k<<<256, 256>>>();

    gemm_out_chalf<<<dim3(8, 8, 4), 256>>>(W_out);
    reduce_out_k<<<256, 256>>>(b_out, out);
}

// round 16
// speedup vs baseline: 1.4334x; 1.0246x over previous
#include <cuda_runtime.h>
#include <math.h>

#define BATCH 4
#define TQL   128
#define TKL   512
#define ND    512
#define OD    512
#define MROWS (BATCH * TQL)     // 512
#define SLAB  (MROWS * 512)     // one partial slab

// Scratch (device globals -- no allocation allowed)
__device__ __align__(16) float g_ctx   [MROWS * ND];
__device__ __align__(16) float g_scores[MROWS * TKL];   // exp(score) (unnormalized)
__device__ __align__(16) float g_ssum  [MROWS * 2];     // per-row half-sums of exp
__device__ __align__(16) float g_part  [4 * SLAB];      // attq partials, then ctx partials (4 slabs)
__device__ __align__(16) float g_part2 [6 * SLAB];      // out-GEMM partials (qhalf 0-1, chalf 2-5)

__device__ __forceinline__ float fast_tanh(float x) {
    float y;
    asm("tanh.approx.f32 %0, %1;" : "=f"(y) : "f"(x));
    return y;
}

// ----------------------------------------------------------------------------
// Split-K NT GEMM body over a K=512 range:
//   part[z0+bz][m][n] = sum_{k in chunk bz} A0[m,k] * B[n, boff+k]
// 64x64 tile, BK=16, 256 threads, 4x4 micro-tile, double-buffered smem.
// ----------------------------------------------------------------------------
template <int SPLITS>
__device__ __forceinline__ void gemm_body(
    const float* __restrict__ A0, const float* __restrict__ B,
    int bstride, int boff, float* __restrict__ part, int z0,
    int bx, int by, int bz)
{
    constexpr int CHUNK  = 512 / SPLITS;
    constexpr int STAGES = CHUNK / 16;

    __shared__ float As[2][16][68];
    __shared__ float Bs[2][16][68];

    const int tid = threadIdx.x;
    const int r   = tid >> 2;
    const int c   = tid & 3;
    const int ty  = tid >> 4;
    const int tx  = tid & 15;
    const int m0  = by * 64;
    const int n0  = bx * 64;
    const int kst = bz * CHUNK;

    float acc[4][4] = {};

    {
        float4 av = *(const float4*)(A0 + (size_t)(m0 + r) * 512 + kst + 4 * c);
        float4 bv = *(const float4*)(B + (size_t)(n0 + r) * bstride + boff + kst + 4 * c);
        float a4[4] = {av.x, av.y, av.z, av.w};
        float b4[4] = {bv.x, bv.y, bv.z, bv.w};
#pragma unroll
        for (int j = 0; j < 4; j++) {
            As[0][4 * c + j][r] = a4[j];
            Bs[0][4 * c + j][r] = b4[j];
        }
    }
    __syncthreads();

    int buf = 0;
#pragma unroll 1
    for (int s = 0; s < STAGES; s++) {
        float4 anx, bnx;
        if (s + 1 < STAGES) {
            const int kb = kst + (s + 1) * 16;
            anx = *(const float4*)(A0 + (size_t)(m0 + r) * 512 + kb + 4 * c);
            bnx = *(const float4*)(B + (size_t)(n0 + r) * bstride + boff + kb + 4 * c);
        }

#pragma unroll
        for (int kk = 0; kk < 16; kk++) {
            float4 a = *(const float4*)&As[buf][kk][ty * 4];
            float4 b = *(const float4*)&Bs[buf][kk][tx * 4];
            float a4[4] = {a.x, a.y, a.z, a.w};
            float b4[4] = {b.x, b.y, b.z, b.w};
#pragma unroll
            for (int i = 0; i < 4; i++)
#pragma unroll
                for (int j = 0; j < 4; j++)
                    acc[i][j] += a4[i] * b4[j];
        }

        if (s + 1 < STAGES) {
            const int nb = buf ^ 1;
            float a4[4] = {anx.x, anx.y, anx.z, anx.w};
            float b4[4] = {bnx.x, bnx.y, bnx.z, bnx.w};
#pragma unroll
            for (int j = 0; j < 4; j++) {
                As[nb][4 * c + j][r] = a4[j];
                Bs[nb][4 * c + j][r] = b4[j];
            }
            __syncthreads();
            buf = nb;
        }
    }

    float* pp = part + (size_t)(z0 + bz) * SLAB;
#pragma unroll
    for (int i = 0; i < 4; i++) {
        float4 v = make_float4(acc[i][0], acc[i][1], acc[i][2], acc[i][3]);
        *(float4*)&pp[(size_t)(m0 + ty * 4 + i) * 512 + n0 + tx * 4] = v;
    }
}

// ----------------------------------------------------------------------------
// Scores body (4 queries x 256 keys per block) with fused attq reduce (4
// slabs) and max-free exp: writes exp(score) to g_scores and per-row-half
// sums to g_ssum. (Scores bounded by sum|w_att| ~ 8.3 -> exp is fp32-safe.)
// ----------------------------------------------------------------------------
__device__ __forceinline__ void scores_body(
    const float* __restrict__ keys,
    const float* __restrict__ w_att,
    const float* __restrict__ b_att,
    const float* __restrict__ b_q,
    int bi)
{
    __shared__ float s_aq[4][512];   // 8 KB
    __shared__ float s_sc[4][256];   // 4 KB (exp scores, this key-half)

    const int tid  = threadIdx.x;
    const int wid  = tid >> 5;
    const int lane = tid & 31;
    const int kh   = bi & 1;
    const int q0   = ((bi >> 1) & 31) << 2;
    const int b    = bi >> 6;

    // 1) fused split-K reduce of att_query (4 slabs, vectorized)
#pragma unroll
    for (int e = 0; e < 2; e++) {
        const int f  = tid + 256 * e;      // float4 index 0..511
        const int q  = f >> 7, ng = f & 127;
        const size_t row4 = ((size_t)(b * TQL + q0 + q) * 512) / 4 + ng;
        float4 s = ((const float4*)b_q)[ng];
#pragma unroll
        for (int sp = 0; sp < 4; sp++) {
            float4 t = ((const float4*)g_part)[(size_t)sp * (SLAB / 4) + row4];
            s.x += t.x; s.y += t.y; s.z += t.z; s.w += t.w;
        }
        *(float4*)&s_aq[q][ng * 4] = s;
    }
    __syncthreads();

    // 2) register-resident w_att + att_query (lane owns 16 n-positions)
    float wreg[16];
    float areg[4][16];
#pragma unroll
    for (int i = 0; i < 4; i++) {
        float4 w4 = *(const float4*)(w_att + i * 128 + lane * 4);
        wreg[i * 4 + 0] = w4.x; wreg[i * 4 + 1] = w4.y;
        wreg[i * 4 + 2] = w4.z; wreg[i * 4 + 3] = w4.w;
#pragma unroll
        for (int q = 0; q < 4; q++) {
            float4 a4 = *(const float4*)&s_aq[q][i * 128 + lane * 4];
            areg[q][i * 4 + 0] = a4.x; areg[q][i * 4 + 1] = a4.y;
            areg[q][i * 4 + 2] = a4.z; areg[q][i * 4 + 3] = a4.w;
        }
    }
    const float batt = b_att[0];
    const float* keyb = keys + (size_t)b * TKL * ND;
    float* sco = g_scores + (size_t)(b * TQL + q0) * TKL;

    // 3) scores + exp (MUFU tanh bound)
    const int kend = kh * 256 + 256;
    for (int k = kh * 256 + wid; k < kend; k += 8) {
        const float* kr = keyb + (size_t)k * ND;
        float acc0 = 0.f, acc1 = 0.f, acc2 = 0.f, acc3 = 0.f;
#pragma unroll
        for (int i = 0; i < 4; i++) {
            float4 k4 = *(const float4*)(kr + i * 128 + lane * 4);
            float kv[4] = {k4.x, k4.y, k4.z, k4.w};
#pragma unroll
            for (int j = 0; j < 4; j++) {
                const float w = wreg[i * 4 + j];
                acc0 += w * fast_tanh(areg[0][i * 4 + j] + kv[j]);
                acc1 += w * fast_tanh(areg[1][i * 4 + j] + kv[j]);
                acc2 += w * fast_tanh(areg[2][i * 4 + j] + kv[j]);
                acc3 += w * fast_tanh(areg[3][i * 4 + j] + kv[j]);
            }
        }
#pragma unroll
        for (int off = 16; off; off >>= 1) {
            acc0 += __shfl_xor_sync(0xffffffffu, acc0, off);
            acc1 += __shfl_xor_sync(0xffffffffu, acc1, off);
            acc2 += __shfl_xor_sync(0xffffffffu, acc2, off);
            acc3 += __shfl_xor_sync(0xffffffffu, acc3, off);
        }
        if (lane == 0) {
            const int kl = k - kh * 256;
            float e0 = __expf(acc0 + batt);
            float e1 = __expf(acc1 + batt);
            float e2 = __expf(acc2 + batt);
            float e3 = __expf(acc3 + batt);
            s_sc[0][kl] = e0; sco[0 * TKL + k] = e0;
            s_sc[1][kl] = e1; sco[1 * TKL + k] = e1;
            s_sc[2][kl] = e2; sco[2 * TKL + k] = e2;
            s_sc[3][kl] = e3; sco[3 * TKL + k] = e3;
        }
    }
    __syncthreads();

    // 4) per-row-half exp sums (warps 0-3, one row each)
    if (wid < 4) {
        float s = 0.f;
#pragma unroll
        for (int i = 0; i < 8; i++) s += s_sc[wid][lane + 32 * i];
#pragma unroll
        for (int off = 16; off; off >>= 1) s += __shfl_xor_sync(0xffffffffu, s, off);
        if (lane == 0)
            g_ssum[(size_t)(b * TQL + q0 + wid) * 2 + kh] = s;
    }
}

// ----------------------------------------------------------------------------
// MEGA: blocks [0,256) = scores+exp (MUFU-bound);
//       blocks [256,384) = out-GEMM query-half, splits=2 (FFMA, hidden).
// ----------------------------------------------------------------------------
__global__ __launch_bounds__(256) void mega_scores_qgemm(
    const float* __restrict__ keys,
    const float* __restrict__ w_att,
    const float* __restrict__ b_att,
    const float* __restrict__ b_q,
    const float* __restrict__ query,
    const float* __restrict__ W_out)
{
    if (blockIdx.x < 256) {
        scores_body(keys, w_att, b_att, b_q, blockIdx.x);
    } else {
        const int g = blockIdx.x - 256;      // 128 = 8n x 8m x 2z
        gemm_body<2>(query, W_out, 1024, 0, g_part2, 0,
                     g & 7, (g >> 3) & 7, g >> 6);
    }
}

// ----------------------------------------------------------------------------
// Standalone GEMM kernels (splits = 4, grid 8x8x4 = 256, 3 CTAs/SM)
// ----------------------------------------------------------------------------
__global__ __launch_bounds__(256, 3) void gemm_attq(
    const float* __restrict__ query, const float* __restrict__ W_q)
{
    gemm_body<4>(query, W_q, 512, 0, g_part, 0, blockIdx.x, blockIdx.y, blockIdx.z);
}

__global__ __launch_bounds__(256, 3) void gemm_out_chalf(const float* __restrict__ W_out)
{
    gemm_body<4>(g_ctx, W_out, 1024, 512, g_part2, 2, blockIdx.x, blockIdx.y, blockIdx.z);
}

// ----------------------------------------------------------------------------
// Split-K NN GEMM for context with FUSED softmax normalization (splits=4):
//   part[z][m][n] = sum_k (exp_sc[m,k] / rowsum[m]) * V_b[k,n]
// A-tiles are scaled by 1/rowsum at load; bx==0 blocks also write the
// normalized chunk to probs.
// ----------------------------------------------------------------------------
template <int SPLITS>
__global__ __launch_bounds__(256, 3) void gemm_ctx_splitk(
    const float* __restrict__ values,
    float* __restrict__ probs)
{
    constexpr int CHUNK  = TKL / SPLITS;
    constexpr int STAGES = CHUNK / 16;

    __shared__ float As[2][16][68];
    __shared__ float Bs[2][16][68];

    const int tid = threadIdx.x;
    const int r   = tid >> 2;
    const int c   = tid & 3;
    const int bk  = tid >> 4;
    const int bn  = (tid & 15) * 4;
    const int ty  = tid >> 4;
    const int tx  = tid & 15;
    const int m0  = blockIdx.y * 64;
    const int n0  = blockIdx.x * 64;
    const int kst = blockIdx.z * CHUNK;
    const bool wp = (blockIdx.x == 0);

    const float* valb = values + (size_t)(m0 >> 7) * TKL * ND;
    const float* P = g_scores;

    const int mrow = m0 + r;
    const float inv = 1.0f / (g_ssum[2 * mrow] + g_ssum[2 * mrow + 1]);

    float acc[4][4] = {};

    {
        float4 av = *(const float4*)(P + (size_t)mrow * TKL + kst + 4 * c);
        float4 bvv = *(const float4*)(valb + (size_t)(kst + bk) * ND + n0 + bn);
        float a4[4] = {av.x * inv, av.y * inv, av.z * inv, av.w * inv};
#pragma unroll
        for (int j = 0; j < 4; j++) As[0][4 * c + j][r] = a4[j];
        if (wp)
            *(float4*)(probs + (size_t)mrow * TKL + kst + 4 * c) =
                make_float4(a4[0], a4[1], a4[2], a4[3]);
        *(float4*)&Bs[0][bk][bn] = bvv;
    }
    __syncthreads();

    int buf = 0;
#pragma unroll 1
    for (int s = 0; s < STAGES; s++) {
        float4 anx, bnx;
        if (s + 1 < STAGES) {
            const int kb = kst + (s + 1) * 16;
            anx = *(const float4*)(P + (size_t)mrow * TKL + kb + 4 * c);
            bnx = *(const float4*)(valb + (size_t)(kb + bk) * ND + n0 + bn);
        }

#pragma unroll
        for (int kk = 0; kk < 16; kk++) {
            float4 a = *(const float4*)&As[buf][kk][ty * 4];
            float4 b = *(const float4*)&Bs[buf][kk][tx * 4];
            float a4[4] = {a.x, a.y, a.z, a.w};
            float b4[4] = {b.x, b.y, b.z, b.w};
#pragma unroll
            for (int i = 0; i < 4; i++)
#pragma unroll
                for (int j = 0; j < 4; j++)
                    acc[i][j] += a4[i] * b4[j];
        }

        if (s + 1 < STAGES) {
            const int nb = buf ^ 1;
            const int kb = kst + (s + 1) * 16;
            float a4[4] = {anx.x * inv, anx.y * inv, anx.z * inv, anx.w * inv};
#pragma unroll
            for (int j = 0; j < 4; j++) As[nb][4 * c + j][r] = a4[j];
            if (wp)
                *(float4*)(probs + (size_t)mrow * TKL + kb + 4 * c) =
                    make_float4(a4[0], a4[1], a4[2], a4[3]);
            *(float4*)&Bs[nb][bk][bn] = bnx;
            __syncthreads();
            buf = nb;
        }
    }

    float* pp = g_part + (size_t)blockIdx.z * SLAB;
#pragma unroll
    for (int i = 0; i < 4; i++) {
        float4 v = make_float4(acc[i][0], acc[i][1], acc[i][2], acc[i][3]);
        *(float4*)&pp[(size_t)(m0 + ty * 4 + i) * 512 + n0 + tx * 4] = v;
    }
}

// ----------------------------------------------------------------------------
// Reductions: ctx sums 4 slabs of g_part; out sums 6 slabs of g_part2.
// ----------------------------------------------------------------------------
__global__ __launch_bounds__(256) void reduce_ctx_k()
{
    const int idx = blockIdx.x * 256 + threadIdx.x;
    const float4* p = (const float4*)g_part;
    float4 s = p[idx];
#pragma unroll
    for (int sp = 1; sp < 4; sp++) {
        float4 t = p[(size_t)sp * (SLAB / 4) + idx];
        s.x += t.x; s.y += t.y; s.z += t.z; s.w += t.w;
    }
    ((float4*)g_ctx)[idx] = s;
}

__global__ __launch_bounds__(256) void reduce_out_k(
    const float* __restrict__ bias, float* __restrict__ dext)
{
    const int idx = blockIdx.x * 256 + threadIdx.x;
    const float4* p = (const float4*)g_part2;
    float4 s = p[idx];
#pragma unroll
    for (int sp = 1; sp < 6; sp++) {
        float4 t = p[(size_t)sp * (SLAB / 4) + idx];
        s.x += t.x; s.y += t.y; s.z += t.z; s.w += t.w;
    }
    const float4 bb = ((const float4*)bias)[idx & (512 / 4 - 1)];
    s.x = tanhf(s.x + bb.x); s.y = tanhf(s.y + bb.y);
    s.z = tanhf(s.z + bb.z); s.w = tanhf(s.w + bb.w);
    ((float4*)dext)[idx] = s;
}

// ----------------------------------------------------------------------------
// Launch sequence (graph-capturable, allocation-free):
//   1) gemm_attq:  query @ W_q^T partials (4 slabs)     -> g_part[0..3]
//   2) MEGA:       scores + exp + row-half sums         -> g_scores, g_ssum
//                  || out-GEMM query-half (2 slabs)     -> g_part2[0..1]
//   3) gemm_ctx:   (exp/rowsum) @ values (4 slabs)      -> g_part[0..3]
//                  (bx==0 blocks also emit probs output)
//   4) reduce_ctx (4 slabs)                             -> g_ctx
//   5) out-GEMM ctx-half (4 slabs)                      -> g_part2[2..5]
//   6) reduce_out: 6 slabs + b_out + tanh               -> out (output)
// ----------------------------------------------------------------------------
extern "C" void kernel_launch(void* const* d_in, const int* in_sizes, int n_in,
                              void* d_out, int out_size)
{
    const float* query  = (const float*)d_in[0];
    const float* keys   = (const float*)d_in[1];
    const float* values = (const float*)d_in[2];
    const float* W_q    = (const float*)d_in[3];
    const float* b_q    = (const float*)d_in[4];
    const float* w_att  = (const float*)d_in[5];
    const float* b_att  = (const float*)d_in[6];
    const float* W_out  = (const float*)d_in[7];
    const float* b_out  = (const float*)d_in[8];

    float* out   = (float*)d_out;
    float* probs = out + (size_t)MROWS * OD;

    gemm_attq<<<dim3(8, 8, 4), 256>>>(query, W_q);

    mega_scores_qgemm<<<384, 256>>>(keys, w_att, b_att, b_q, query, W_out);

    gemm_ctx_splitk<4><<<dim3(8, 8, 4), 256>>>(values, probs);
    reduce_ctx_k<<<256, 256>>>();

    gemm_out_chalf<<<dim3(8, 8, 4), 256>>>(W_out);
    reduce_out_k<<<256, 256>>>(b_out, out);
}